// round 1
// baseline (speedup 1.0000x reference)
#include <cuda_runtime.h>
#include <math.h>

// Problem constants (fixed shapes from reference)
#define Bsz 4096
#define Tsz 64
#define Fsz 37
#define TB 8          // batch elements per CTA
#define NP 24         // TB * 3 timesteps
#define NT 512        // threads per CTA
#define LINP 152      // padded lin width (150 -> 152 for float4)
#define GATES 512
#define H 128

// shared memory layout (floats)
#define OFF_FEAT 0        // 24*37 = 888   (aliased by head buffers later)
#define OFF_T1M1 888      // 24*16 = 384
#define OFF_S1   1272     // 24*32 = 768
#define OFF_LIN  2040     // 24*152 = 3648 (16B aligned: 2040*4 = 8160)
#define OFF_Z    5688     // 8*512 = 4096
#define OFF_H    9784     // 8*128 = 1024 (16B aligned)
#define OFF_C    10808    // 8*128 = 1024
#define SMEM_FLOATS 11832 // 47328 bytes < 48KB static limit

struct Params {
    const float *feature;
    const float *w_m1, *b_m1, *w_m2, *b_m2;
    const float *w_t1, *b_t1, *w_t2, *b_t2;
    const float *w_s1, *b_s1, *w_s2, *b_s2;
    const float *w_lk, *w_lr, *b_l;
    const float *w_p1, *b_p1, *w_p2, *b_p2, *w_p3, *b_p3, *w_p4, *b_p4, *w_p5, *b_p5;
    float *out;
};

__device__ __forceinline__ float lrelu(float x) { return x >= 0.f ? x : 0.2f * x; }
__device__ __forceinline__ float sigm(float x) { return 1.f / (1.f + expf(-x)); }

__global__ void __launch_bounds__(NT) lstm_fused_kernel(Params P) {
    __shared__ __align__(16) float sm[SMEM_FLOATS];
    const int tid = threadIdx.x;
    const int bg0 = blockIdx.x * TB;

    float *feat = sm + OFF_FEAT;
    float *t1m1 = sm + OFF_T1M1;
    float *S1   = sm + OFF_S1;
    float *lin  = sm + OFF_LIN;
    float *zbuf = sm + OFF_Z;
    float *hbuf = sm + OFF_H;
    float *cbuf = sm + OFF_C;

    // ---- load feature rows t=0..2 for 8 batch elems; zero h,c ----
    for (int i = tid; i < NP * Fsz; i += NT) {
        int p = i / Fsz, f = i % Fsz;
        int b = p / 3, t = p % 3;
        feat[p * Fsz + f] =
            P.feature[(size_t)(bg0 + b) * Tsz * Fsz + (size_t)t * Fsz + f];
    }
    for (int i = tid; i < TB * H; i += NT) { hbuf[i] = 0.f; cbuf[i] = 0.f; }
    __syncthreads();

    // ---- pass1: M1 (q<8) and T1 (q>=8), per (b,t) pair p ----
    for (int i = tid; i < NP * 16; i += NT) {
        int p = i >> 4, q = i & 15;
        const float *fr = feat + p * Fsz;
        float acc;
        if (q < 8) {
            acc = P.b_m1[q];
            #pragma unroll
            for (int f = 0; f < 3; ++f) acc += fr[33 + f] * P.w_m1[f * 8 + q];
            acc = lrelu(acc);
        } else {
            int j = q - 8;
            acc = P.b_t1[j];
            #pragma unroll
            for (int f = 0; f < Fsz; ++f) acc += fr[f] * P.w_t1[f * 8 + j];
            acc = lrelu(acc);
            acc = fabsf(acc);
        }
        t1m1[i] = acc;
    }
    __syncthreads();

    // ---- pass2: M -> lin[0:16], Tsk -> lin[16:32], Psk -> lin[32:48] ----
    for (int i = tid; i < NP * 32; i += NT) {
        int p = i >> 5, q = i & 31;
        float *lp = lin + p * LINP;
        if (q < 16) {
            float acc = P.b_m2[q];
            #pragma unroll
            for (int k = 0; k < 8; ++k) acc += t1m1[p * 16 + k] * P.w_m2[k * 16 + q];
            lp[q] = lrelu(acc);
        } else {
            int j = q - 16;
            float acc = P.b_t2[j];
            #pragma unroll
            for (int k = 0; k < 8; ++k) acc += t1m1[p * 16 + 8 + k] * P.w_t2[k * 16 + j];
            // abs(lrelu(x)) : x>=0 ? x : -0.2x
            float v = (acc >= 0.f) ? acc : -0.2f * acc;
            lp[16 + j] = v;
            lp[32 + j] = log1pf(v);
        }
    }
    // Pa -> lin[48], feature copy -> lin[113:150]
    for (int i = tid; i < NP * 38; i += NT) {
        int p = i / 38, q = i % 38;
        if (q == 0) lin[p * LINP + 48] = log1pf(feat[p * Fsz + 31]);
        else        lin[p * LINP + 113 + (q - 1)] = feat[p * Fsz + (q - 1)];
    }
    __syncthreads();

    // ---- pass3: S1 = lrelu(s_in @ w_s1 + b_s1) ----
    // s_in[0:49] == lin[0:49]; s_in[49:55]=env=feat[27:33]; s_in[55:58]=body=feat[33:36]
    for (int i = tid; i < NP * 32; i += NT) {
        int p = i >> 5, j = i & 31;
        float acc = P.b_s1[j];
        const float *lp = lin + p * LINP;
        for (int f = 0; f < 49; ++f) acc += lp[f] * P.w_s1[f * 32 + j];
        const float *fr = feat + p * Fsz;
        #pragma unroll
        for (int e = 0; e < 6; ++e) acc += fr[27 + e] * P.w_s1[(49 + e) * 32 + j];
        #pragma unroll
        for (int e = 0; e < 3; ++e) acc += fr[33 + e] * P.w_s1[(55 + e) * 32 + j];
        S1[p * 32 + j] = lrelu(acc);
    }
    __syncthreads();

    // ---- pass4: S -> lin[49:113] ----
    for (int i = tid; i < NP * 64; i += NT) {
        int p = i >> 6, j = i & 63;
        float acc = P.b_s2[j];
        #pragma unroll
        for (int k = 0; k < 32; ++k) acc += S1[p * 32 + k] * P.w_s2[k * 64 + j];
        lin[p * LINP + 49 + j] = lrelu(acc);
    }
    __syncthreads();

    // ---- LSTM: 3 timesteps, gate column j = tid ----
    {
        const int j = tid;
        const float blj = P.b_l[j];
        const float *wk = P.w_lk + j;
        const float *wr = P.w_lr + j;
        for (int t = 0; t < 3; ++t) {
            float zr[TB];
            #pragma unroll
            for (int b = 0; b < TB; ++b) zr[b] = blj;
            // input GEMM: z += lin @ w_lk
            for (int f = 0; f < 148; f += 4) {
                float w0 = __ldg(wk + (size_t)(f + 0) * GATES);
                float w1 = __ldg(wk + (size_t)(f + 1) * GATES);
                float w2 = __ldg(wk + (size_t)(f + 2) * GATES);
                float w3 = __ldg(wk + (size_t)(f + 3) * GATES);
                #pragma unroll
                for (int b = 0; b < TB; ++b) {
                    const float4 lv = *(const float4 *)(lin + (b * 3 + t) * LINP + f);
                    zr[b] += lv.x * w0;
                    zr[b] += lv.y * w1;
                    zr[b] += lv.z * w2;
                    zr[b] += lv.w * w3;
                }
            }
            {
                float w0 = __ldg(wk + (size_t)148 * GATES);
                float w1 = __ldg(wk + (size_t)149 * GATES);
                #pragma unroll
                for (int b = 0; b < TB; ++b) {
                    const float2 lv = *(const float2 *)(lin + (b * 3 + t) * LINP + 148);
                    zr[b] += lv.x * w0 + lv.y * w1;
                }
            }
            // recurrent GEMM: z += h @ w_lr (h == 0 at t=0, skip)
            if (t > 0) {
                for (int k = 0; k < H; k += 4) {
                    float w0 = __ldg(wr + (size_t)(k + 0) * GATES);
                    float w1 = __ldg(wr + (size_t)(k + 1) * GATES);
                    float w2 = __ldg(wr + (size_t)(k + 2) * GATES);
                    float w3 = __ldg(wr + (size_t)(k + 3) * GATES);
                    #pragma unroll
                    for (int b = 0; b < TB; ++b) {
                        const float4 hv = *(const float4 *)(hbuf + b * H + k);
                        zr[b] += hv.x * w0;
                        zr[b] += hv.y * w1;
                        zr[b] += hv.z * w2;
                        zr[b] += hv.w * w3;
                    }
                }
            }
            #pragma unroll
            for (int b = 0; b < TB; ++b) zbuf[b * GATES + j] = zr[b];
            __syncthreads();
            // gate nonlinearity + state update
            for (int idx = tid; idx < TB * H; idx += NT) {
                int b = idx >> 7, k = idx & 127;
                const float *zp = zbuf + b * GATES;
                float ig = sigm(zp[k]);
                float fg = sigm(zp[128 + k]);
                float g  = lrelu(zp[256 + k]);
                float og = sigm(zp[384 + k]);
                float cv = fg * cbuf[idx] + ig * g;
                cbuf[idx] = cv;
                hbuf[idx] = og * lrelu(cv);
            }
            __syncthreads();
        }
    }

    // ---- head at t=2 (buffers alias dead front-end smem [0, 1272)) ----
    float *d1 = sm;        // 8*64
    float *d2 = sm + 512;  // 8*32
    float *d3 = sm + 768;  // 8*16
    float *d4 = sm + 896;  // 8*8
    float *d5 = sm + 960;  // 8*3

    for (int i = tid; i < TB * 64; i += NT) {
        int b = i >> 6, j = i & 63;
        float acc = P.b_p1[j];
        for (int k = 0; k < H; ++k) acc += hbuf[b * H + k] * P.w_p1[k * 64 + j];
        d1[i] = lrelu(acc);
    }
    __syncthreads();
    for (int i = tid; i < TB * 32; i += NT) {
        int b = i >> 5, j = i & 31;
        float acc = P.b_p2[j];
        #pragma unroll
        for (int k = 0; k < 64; ++k) acc += d1[b * 64 + k] * P.w_p2[k * 32 + j];
        d2[i] = lrelu(acc);
    }
    __syncthreads();
    for (int i = tid; i < TB * 16; i += NT) {
        int b = i >> 4, j = i & 15;
        float acc = P.b_p3[j];
        #pragma unroll
        for (int k = 0; k < 32; ++k) acc += d2[b * 32 + k] * P.w_p3[k * 16 + j];
        d3[i] = lrelu(acc);
    }
    __syncthreads();
    for (int i = tid; i < TB * 8; i += NT) {
        int b = i >> 3, j = i & 7;
        float acc = P.b_p4[j];
        #pragma unroll
        for (int k = 0; k < 16; ++k) acc += d3[b * 16 + k] * P.w_p4[k * 8 + j];
        d4[i] = lrelu(acc);
    }
    __syncthreads();
    for (int i = tid; i < TB * 3; i += NT) {
        int b = i / 3, j = i % 3;
        float acc = P.b_p5[j];
        #pragma unroll
        for (int k = 0; k < 8; ++k) acc += d4[b * 8 + k] * P.w_p5[k * 3 + j];
        d5[i] = lrelu(acc);
    }
    __syncthreads();

    // ---- softmax + write both outputs ----
    if (tid < TB) {
        int b = tid;
        float l0 = d5[b * 3 + 0], l1 = d5[b * 3 + 1], l2 = d5[b * 3 + 2];
        float m = fmaxf(l0, fmaxf(l1, l2));
        float e0 = expf(l0 - m), e1 = expf(l1 - m), e2 = expf(l2 - m);
        float inv = 1.f / (e0 + e1 + e2);
        float o0 = e0 * inv, o1 = e1 * inv, o2 = e2 * inv;
        size_t gb = (size_t)(bg0 + b);
        // output tensor: (4096, 1, 3) flattened first
        float *outp = P.out + gb * 3;
        outp[0] = o0; outp[1] = o1; outp[2] = o2;
        // x tensor: (4096, 1, 13) = [feature[:,2,27:37], output]
        float *xp = P.out + (size_t)Bsz * 3 + gb * 13;
        const float *fsrc = P.feature + gb * Tsz * Fsz + 2 * Fsz + 27;
        #pragma unroll
        for (int q = 0; q < 10; ++q) xp[q] = fsrc[q];
        xp[10] = o0; xp[11] = o1; xp[12] = o2;
    }
}

extern "C" void kernel_launch(void *const *d_in, const int *in_sizes, int n_in,
                              void *d_out, int out_size) {
    Params P;
    P.feature = (const float *)d_in[0];
    P.w_m1 = (const float *)d_in[1];  P.b_m1 = (const float *)d_in[2];
    P.w_m2 = (const float *)d_in[3];  P.b_m2 = (const float *)d_in[4];
    P.w_t1 = (const float *)d_in[5];  P.b_t1 = (const float *)d_in[6];
    P.w_t2 = (const float *)d_in[7];  P.b_t2 = (const float *)d_in[8];
    P.w_s1 = (const float *)d_in[9];  P.b_s1 = (const float *)d_in[10];
    P.w_s2 = (const float *)d_in[11]; P.b_s2 = (const float *)d_in[12];
    P.w_lk = (const float *)d_in[13];
    P.w_lr = (const float *)d_in[14];
    P.b_l  = (const float *)d_in[15];
    P.w_p1 = (const float *)d_in[16]; P.b_p1 = (const float *)d_in[17];
    P.w_p2 = (const float *)d_in[18]; P.b_p2 = (const float *)d_in[19];
    P.w_p3 = (const float *)d_in[20]; P.b_p3 = (const float *)d_in[21];
    P.w_p4 = (const float *)d_in[22]; P.b_p4 = (const float *)d_in[23];
    P.w_p5 = (const float *)d_in[24]; P.b_p5 = (const float *)d_in[25];
    P.out = (float *)d_out;

    lstm_fused_kernel<<<Bsz / TB, NT>>>(P);
}

// round 3
// speedup vs baseline: 1.5609x; 1.5609x over previous
#include <cuda_runtime.h>
#include <math.h>

#define Bsz 4096
#define Tsz 64
#define Fsz 37
#define TB 8          // batch elements per CTA
#define NP 24         // TB * 3 timesteps
#define NT 128        // threads per CTA (one per hidden unit)
#define FDIM 150      // lin width
#define GATES 512
#define H 128

typedef unsigned long long ull;

// shared memory layout (floats)
#define OFF_FEAT 0        // 24*37 = 888  (aliased by head buffers later)
#define OFF_T1M1 888      // 24*16 = 384
#define OFF_S1   1272     // 24*32 = 768
#define OFF_LIN  2040     // 3*150*8 = 3600  (byte off 8160, 32B aligned)
#define OFF_H    5640     // 128*8 = 1024    (byte off 22560, 32B aligned)
#define SMEM_FLOATS 6664  // 26656 bytes

struct Params {
    const float *feature;
    const float *w_m1, *b_m1, *w_m2, *b_m2;
    const float *w_t1, *b_t1, *w_t2, *b_t2;
    const float *w_s1, *b_s1, *w_s2, *b_s2;
    const float *w_lk, *w_lr, *b_l;
    const float *w_p1, *b_p1, *w_p2, *b_p2, *w_p3, *b_p3, *w_p4, *b_p4, *w_p5, *b_p5;
    float *out;
};

__device__ __forceinline__ float lrelu(float x) { return x >= 0.f ? x : 0.2f * x; }
__device__ __forceinline__ float sigm(float x) { return 1.f / (1.f + __expf(-x)); }

__device__ __forceinline__ ull pack2(float lo, float hi) {
    ull v;
    asm("mov.b64 %0, {%1, %2};" : "=l"(v) : "f"(lo), "f"(hi));
    return v;
}
__device__ __forceinline__ void unpack2(float &lo, float &hi, ull v) {
    asm("mov.b64 {%0, %1}, %2;" : "=f"(lo), "=f"(hi) : "l"(v));
}
__device__ __forceinline__ void ffma2(ull &acc, ull a, ull b) {
    asm("fma.rn.f32x2 %0, %1, %2, %0;" : "+l"(acc) : "l"(a), "l"(b));
}

// lin transposed: [t][f][b], b contiguous (8 floats = 32B per row)
#define LIDX(t, f, b) (((t) * FDIM + (f)) * TB + (b))

__global__ void __launch_bounds__(NT) lstm_fused_kernel(Params P) {
    __shared__ __align__(32) float sm[SMEM_FLOATS];
    const int tid = threadIdx.x;
    const int bg0 = blockIdx.x * TB;

    float *feat = sm + OFF_FEAT;
    float *t1m1 = sm + OFF_T1M1;
    float *S1   = sm + OFF_S1;
    float *linT = sm + OFF_LIN;
    float *hT   = sm + OFF_H;

    // ---- load feature rows t=0..2 for 8 batch elems ----
    for (int i = tid; i < NP * Fsz; i += NT) {
        int p = i / Fsz, f = i % Fsz;
        int b = p / 3, t = p % 3;
        feat[p * Fsz + f] =
            P.feature[(size_t)(bg0 + b) * Tsz * Fsz + (size_t)t * Fsz + f];
    }
    __syncthreads();

    // ---- pass1: M1 (q<8) and T1 (q>=8), per (b,t) pair p ----
    for (int i = tid; i < NP * 16; i += NT) {
        int p = i >> 4, q = i & 15;
        const float *fr = feat + p * Fsz;
        float acc;
        if (q < 8) {
            acc = P.b_m1[q];
            #pragma unroll
            for (int f = 0; f < 3; ++f) acc += fr[33 + f] * P.w_m1[f * 8 + q];
            acc = lrelu(acc);
        } else {
            int j = q - 8;
            acc = P.b_t1[j];
            #pragma unroll
            for (int f = 0; f < Fsz; ++f) acc += fr[f] * P.w_t1[f * 8 + j];
            acc = lrelu(acc);
            acc = fabsf(acc);
        }
        t1m1[i] = acc;
    }
    __syncthreads();

    // ---- pass2: M -> lin[0:16], Tsk -> lin[16:32], Psk -> lin[32:48] ----
    for (int i = tid; i < NP * 32; i += NT) {
        int p = i >> 5, q = i & 31;
        int b = p / 3, t = p % 3;
        if (q < 16) {
            float acc = P.b_m2[q];
            #pragma unroll
            for (int k = 0; k < 8; ++k) acc += t1m1[p * 16 + k] * P.w_m2[k * 16 + q];
            linT[LIDX(t, q, b)] = lrelu(acc);
        } else {
            int j = q - 16;
            float acc = P.b_t2[j];
            #pragma unroll
            for (int k = 0; k < 8; ++k) acc += t1m1[p * 16 + 8 + k] * P.w_t2[k * 16 + j];
            float v = (acc >= 0.f) ? acc : -0.2f * acc;  // abs(lrelu)
            linT[LIDX(t, 16 + j, b)] = v;
            linT[LIDX(t, 32 + j, b)] = log1pf(v);
        }
    }
    // Pa -> lin[48], feature copy -> lin[113:150]
    for (int i = tid; i < NP * 38; i += NT) {
        int p = i / 38, q = i % 38;
        int b = p / 3, t = p % 3;
        if (q == 0) linT[LIDX(t, 48, b)] = log1pf(feat[p * Fsz + 31]);
        else        linT[LIDX(t, 113 + (q - 1), b)] = feat[p * Fsz + (q - 1)];
    }
    __syncthreads();

    // ---- pass3: S1 = lrelu(s_in @ w_s1 + b_s1) ----
    for (int i = tid; i < NP * 32; i += NT) {
        int p = i >> 5, j = i & 31;
        int b = p / 3, t = p % 3;
        float acc = P.b_s1[j];
        for (int f = 0; f < 49; ++f) acc += linT[LIDX(t, f, b)] * P.w_s1[f * 32 + j];
        const float *fr = feat + p * Fsz;
        #pragma unroll
        for (int e = 0; e < 6; ++e) acc += fr[27 + e] * P.w_s1[(49 + e) * 32 + j];
        #pragma unroll
        for (int e = 0; e < 3; ++e) acc += fr[33 + e] * P.w_s1[(55 + e) * 32 + j];
        S1[p * 32 + j] = lrelu(acc);
    }
    __syncthreads();

    // ---- pass4: S -> lin[49:113] ----
    for (int i = tid; i < NP * 64; i += NT) {
        int p = i >> 6, j = i & 63;
        int b = p / 3, t = p % 3;
        float acc = P.b_s2[j];
        #pragma unroll
        for (int k = 0; k < 32; ++k) acc += S1[p * 32 + k] * P.w_s2[k * 64 + j];
        linT[LIDX(t, 49 + j, b)] = lrelu(acc);
    }
    __syncthreads();

    // ---- LSTM: 3 timesteps. Thread tid owns hidden unit k=tid, i.e. gate
    // columns tid, tid+128, tid+256, tid+384 (= i,f,g,o of unit tid).
    // Batches packed in f32x2 pairs; c-state register-resident.
    {
        const int j = tid;
        ull biad[4];
        #pragma unroll
        for (int c = 0; c < 4; ++c) {
            float bv = P.b_l[j + c * H];
            biad[c] = pack2(bv, bv);
        }
        float cres[TB];
        #pragma unroll
        for (int b = 0; b < TB; ++b) cres[b] = 0.f;

        const float *wk = P.w_lk + j;
        const float *wr = P.w_lr + j;

        for (int t = 0; t < 3; ++t) {
            ull acc[4][4];
            #pragma unroll
            for (int c = 0; c < 4; ++c)
                #pragma unroll
                for (int p = 0; p < 4; ++p) acc[c][p] = biad[c];

            // input GEMM: z += lin_t @ w_lk
            #pragma unroll 2
            for (int f = 0; f < FDIM; ++f) {
                const float4 *lp = (const float4 *)(linT + (t * FDIM + f) * TB);
                float4 a0 = lp[0];
                float4 a1 = lp[1];
                ull lv0 = pack2(a0.x, a0.y);
                ull lv1 = pack2(a0.z, a0.w);
                ull lv2 = pack2(a1.x, a1.y);
                ull lv3 = pack2(a1.z, a1.w);
                #pragma unroll
                for (int c = 0; c < 4; ++c) {
                    float w = __ldg(wk + f * GATES + c * H);
                    ull wd = pack2(w, w);
                    ffma2(acc[c][0], lv0, wd);
                    ffma2(acc[c][1], lv1, wd);
                    ffma2(acc[c][2], lv2, wd);
                    ffma2(acc[c][3], lv3, wd);
                }
            }
            // recurrent GEMM: z += h @ w_lr  (h == 0 at t=0)
            if (t > 0) {
                #pragma unroll 2
                for (int f = 0; f < H; ++f) {
                    const float4 *hp = (const float4 *)(hT + f * TB);
                    float4 a0 = hp[0];
                    float4 a1 = hp[1];
                    ull lv0 = pack2(a0.x, a0.y);
                    ull lv1 = pack2(a0.z, a0.w);
                    ull lv2 = pack2(a1.x, a1.y);
                    ull lv3 = pack2(a1.z, a1.w);
                    #pragma unroll
                    for (int c = 0; c < 4; ++c) {
                        float w = __ldg(wr + f * GATES + c * H);
                        ull wd = pack2(w, w);
                        ffma2(acc[c][0], lv0, wd);
                        ffma2(acc[c][1], lv1, wd);
                        ffma2(acc[c][2], lv2, wd);
                        ffma2(acc[c][3], lv3, wd);
                    }
                }
            }

            // all reads of hT (this t) must finish before we overwrite it
            __syncthreads();

            // gates + state update, fully in registers
            float hv[TB];
            #pragma unroll
            for (int p = 0; p < 4; ++p) {
                float zi0, zi1, zf0, zf1, zg0, zg1, zo0, zo1;
                unpack2(zi0, zi1, acc[0][p]);
                unpack2(zf0, zf1, acc[1][p]);
                unpack2(zg0, zg1, acc[2][p]);
                unpack2(zo0, zo1, acc[3][p]);
                int b0 = 2 * p, b1 = 2 * p + 1;
                float c0 = sigm(zf0) * cres[b0] + sigm(zi0) * lrelu(zg0);
                float c1 = sigm(zf1) * cres[b1] + sigm(zi1) * lrelu(zg1);
                cres[b0] = c0;
                cres[b1] = c1;
                hv[b0] = sigm(zo0) * lrelu(c0);
                hv[b1] = sigm(zo1) * lrelu(c1);
            }
            float4 *hrow = (float4 *)(hT + j * TB);
            hrow[0] = make_float4(hv[0], hv[1], hv[2], hv[3]);
            hrow[1] = make_float4(hv[4], hv[5], hv[6], hv[7]);
            __syncthreads();
        }
    }

    // ---- head at t=2 (buffers alias dead front-end smem) ----
    float *d1 = sm;        // 8*64
    float *d2 = sm + 512;  // 8*32
    float *d3 = sm + 768;  // 8*16
    float *d4 = sm + 896;  // 8*8
    float *d5 = sm + 960;  // 8*3

    for (int i = tid; i < TB * 64; i += NT) {
        int b = i >> 6, j = i & 63;
        float acc = P.b_p1[j];
        for (int k = 0; k < H; ++k) acc += hT[k * TB + b] * P.w_p1[k * 64 + j];
        d1[i] = lrelu(acc);
    }
    __syncthreads();
    for (int i = tid; i < TB * 32; i += NT) {
        int b = i >> 5, j = i & 31;
        float acc = P.b_p2[j];
        #pragma unroll
        for (int k = 0; k < 64; ++k) acc += d1[b * 64 + k] * P.w_p2[k * 32 + j];
        d2[i] = lrelu(acc);
    }
    __syncthreads();
    for (int i = tid; i < TB * 16; i += NT) {
        int b = i >> 4, j = i & 15;
        float acc = P.b_p3[j];
        #pragma unroll
        for (int k = 0; k < 32; ++k) acc += d2[b * 32 + k] * P.w_p3[k * 16 + j];
        d3[i] = lrelu(acc);
    }
    __syncthreads();
    for (int i = tid; i < TB * 8; i += NT) {
        int b = i >> 3, j = i & 7;
        float acc = P.b_p4[j];
        #pragma unroll
        for (int k = 0; k < 16; ++k) acc += d3[b * 16 + k] * P.w_p4[k * 8 + j];
        d4[i] = lrelu(acc);
    }
    __syncthreads();
    for (int i = tid; i < TB * 3; i += NT) {
        int b = i / 3, j = i % 3;
        float acc = P.b_p5[j];
        #pragma unroll
        for (int k = 0; k < 8; ++k) acc += d4[b * 8 + k] * P.w_p5[k * 3 + j];
        d5[i] = lrelu(acc);
    }
    __syncthreads();

    // ---- softmax + write both outputs ----
    if (tid < TB) {
        int b = tid;
        float l0 = d5[b * 3 + 0], l1 = d5[b * 3 + 1], l2 = d5[b * 3 + 2];
        float m = fmaxf(l0, fmaxf(l1, l2));
        float e0 = __expf(l0 - m), e1 = __expf(l1 - m), e2 = __expf(l2 - m);
        float inv = 1.f / (e0 + e1 + e2);
        float o0 = e0 * inv, o1 = e1 * inv, o2 = e2 * inv;
        size_t gb = (size_t)(bg0 + b);
        float *outp = P.out + gb * 3;
        outp[0] = o0; outp[1] = o1; outp[2] = o2;
        float *xp = P.out + (size_t)Bsz * 3 + gb * 13;
        const float *fsrc = P.feature + gb * Tsz * Fsz + 2 * Fsz + 27;
        #pragma unroll
        for (int q = 0; q < 10; ++q) xp[q] = fsrc[q];
        xp[10] = o0; xp[11] = o1; xp[12] = o2;
    }
}

extern "C" void kernel_launch(void *const *d_in, const int *in_sizes, int n_in,
                              void *d_out, int out_size) {
    Params P;
    P.feature = (const float *)d_in[0];
    P.w_m1 = (const float *)d_in[1];  P.b_m1 = (const float *)d_in[2];
    P.w_m2 = (const float *)d_in[3];  P.b_m2 = (const float *)d_in[4];
    P.w_t1 = (const float *)d_in[5];  P.b_t1 = (const float *)d_in[6];
    P.w_t2 = (const float *)d_in[7];  P.b_t2 = (const float *)d_in[8];
    P.w_s1 = (const float *)d_in[9];  P.b_s1 = (const float *)d_in[10];
    P.w_s2 = (const float *)d_in[11]; P.b_s2 = (const float *)d_in[12];
    P.w_lk = (const float *)d_in[13];
    P.w_lr = (const float *)d_in[14];
    P.b_l  = (const float *)d_in[15];
    P.w_p1 = (const float *)d_in[16]; P.b_p1 = (const float *)d_in[17];
    P.w_p2 = (const float *)d_in[18]; P.b_p2 = (const float *)d_in[19];
    P.w_p3 = (const float *)d_in[20]; P.b_p3 = (const float *)d_in[21];
    P.w_p4 = (const float *)d_in[22]; P.b_p4 = (const float *)d_in[23];
    P.w_p5 = (const float *)d_in[24]; P.b_p5 = (const float *)d_in[25];
    P.out = (float *)d_out;

    lstm_fused_kernel<<<Bsz / TB, NT>>>(P);
}